// round 4
// baseline (speedup 1.0000x reference)
#include <cuda_runtime.h>
#include <math.h>

#define NROWS (64*9*374)      // 215424 rows of F=128
#define BT    (64*9)          // 576 (b,t) groups
#define RR    374
#define KSEL  299
#define NBLK1 (NROWS/128)     // 1683 k1 blocks (exact)
#define EPS_TINY 1.17549435082228750797e-38f

typedef unsigned long long u64;

// scratch (static device memory — no runtime allocation)
__device__ __align__(16) float g_local[(size_t)NROWS*64]; // gelu(h1)[:, 0:64]
__device__ float g_part[NBLK1*128];                       // per-block hi partials
__device__ float g_gcon[BT*32];                           // glob @ w2[64:,:]
__device__ float g_scores[NROWS];                         // score + gumbel

__device__ __forceinline__ u64 fma2(u64 a, u64 b, u64 c) {
    u64 d; asm("fma.rn.f32x2 %0,%1,%2,%3;" : "=l"(d) : "l"(a), "l"(b), "l"(c));
    return d;
}
__device__ __forceinline__ void upk2(u64 v, float& lo, float& hi) {
    asm("mov.b64 {%0,%1},%2;" : "=f"(lo), "=f"(hi) : "l"(v));
}
__device__ __forceinline__ float frcp(float x) {
    float r; asm("rcp.approx.ftz.f32 %0,%1;" : "=f"(r) : "f"(x));
    return r;
}
__device__ __forceinline__ float gelu_exact(float x) {
    return 0.5f * x * (1.0f + erff(x * 0.70710678118654752440f));
}

// ---------------------------------------------------------------------------
// Kernel 1: LayerNorm + GEMM1 (128x128) + bias + GELU.
// 512 threads, 128-row tile, 8x4 microtile, f32x2 over K, LDS.128 loads.
// Warp = 32 col-threads of one row-group -> a-loads broadcast (1 phase).
// ---------------------------------------------------------------------------
__global__ void __launch_bounds__(512) k1_ln_gemm1(
    const float* __restrict__ x, const float* __restrict__ ln_w,
    const float* __restrict__ ln_b, const float* __restrict__ w1,
    const float* __restrict__ b1)
{
    extern __shared__ float sm[];
    float* w1t = sm;                      // [128 cols][132]
    float* xs  = sm + 128*132;            // [128 rows][132]
    float* red = sm + 2*128*132;          // [2][64][16]

    const int t  = threadIdx.x;
    const int R0 = blockIdx.x * 128;

    // stage w1 transposed (each thread 8 float4 source reads)
    #pragma unroll
    for (int i = 0; i < 8; i++) {
        int id = i*512 + t;              // k = id/32, c4 = (id%32)*4
        int k  = id >> 5, c4 = (id & 31) << 2;
        float4 v = ((const float4*)w1)[id];
        w1t[(c4+0)*132 + k] = v.x;
        w1t[(c4+1)*132 + k] = v.y;
        w1t[(c4+2)*132 + k] = v.z;
        w1t[(c4+3)*132 + k] = v.w;
    }

    // layernorm: 16 warps x 8 rows
    {
        const int lane = t & 31, w = t >> 5;
        float4 lw = ((const float4*)ln_w)[lane];
        float4 lb = ((const float4*)ln_b)[lane];
        #pragma unroll
        for (int rr = 0; rr < 8; rr++) {
            int r = w*8 + rr;
            float4 xv = ((const float4*)x)[(size_t)(R0 + r)*32 + lane];
            float s = xv.x + xv.y + xv.z + xv.w;
            #pragma unroll
            for (int o = 16; o; o >>= 1) s += __shfl_xor_sync(0xffffffffu, s, o);
            float m = s * (1.0f/128.0f);
            float dx = xv.x - m, dy = xv.y - m, dz = xv.z - m, dw = xv.w - m;
            float q = dx*dx + dy*dy + dz*dz + dw*dw;
            #pragma unroll
            for (int o = 16; o; o >>= 1) q += __shfl_xor_sync(0xffffffffu, q, o);
            float rs = rsqrtf(q * (1.0f/128.0f) + 1e-5f);
            float4 y;
            y.x = dx*rs*lw.x + lb.x;
            y.y = dy*rs*lw.y + lb.y;
            y.z = dz*rs*lw.z + lb.z;
            y.w = dw*rs*lw.w + lb.w;
            *(float4*)(xs + r*132 + lane*4) = y;
        }
    }
    __syncthreads();

    const int rg = t >> 5, tx = t & 31;   // rows rg*8..+7, cols tx + j*32
    u64 acc[8][4];
    #pragma unroll
    for (int i = 0; i < 8; i++)
        #pragma unroll
        for (int j = 0; j < 4; j++) acc[i][j] = 0ULL;

    #pragma unroll 2
    for (int k4 = 0; k4 < 32; k4++) {     // 4 k per iter (2 u64)
        // a: LDS.128, broadcast across warp
        u64 a[8][2];
        #pragma unroll
        for (int i = 0; i < 8; i++) {
            float4 v = *(const float4*)(xs + (rg*8 + i)*132 + k4*4);
            a[i][0] = ((const u64*)&v)[0];
            a[i][1] = ((const u64*)&v)[1];
        }
        // b: LDS.128, 32 distinct columns
        u64 b[4][2];
        #pragma unroll
        for (int j = 0; j < 4; j++) {
            float4 v = *(const float4*)(w1t + (tx + j*32)*132 + k4*4);
            b[j][0] = ((const u64*)&v)[0];
            b[j][1] = ((const u64*)&v)[1];
        }
        #pragma unroll
        for (int i = 0; i < 8; i++)
            #pragma unroll
            for (int j = 0; j < 4; j++) {
                acc[i][j] = fma2(a[i][0], b[j][0], acc[i][j]);
                acc[i][j] = fma2(a[i][1], b[j][1], acc[i][j]);
            }
    }

    float bv[4];
    #pragma unroll
    for (int j = 0; j < 4; j++) bv[j] = b1[tx + j*32];

    const int g0 = R0 / RR;
    const int boundary = (g0 + 1) * RR;
    float part[2][2];
    part[0][0] = part[0][1] = part[1][0] = part[1][1] = 0.0f;

    #pragma unroll
    for (int i = 0; i < 8; i++) {
        int r = R0 + rg*8 + i;
        // local half: cols tx, tx+32
        {
            float lo, hi; upk2(acc[i][0], lo, hi);
            g_local[(size_t)r*64 + tx]      = gelu_exact(lo + hi + bv[0]);
            upk2(acc[i][1], lo, hi);
            g_local[(size_t)r*64 + tx + 32] = gelu_exact(lo + hi + bv[1]);
        }
        // hi half: cols tx+64, tx+96 -> glob partials
        int sd = (r >= boundary) ? 1 : 0;
        float lo, hi;
        upk2(acc[i][2], lo, hi);
        float v0 = gelu_exact(lo + hi + bv[2]);
        upk2(acc[i][3], lo, hi);
        float v1 = gelu_exact(lo + hi + bv[3]);
        if (sd) { part[1][0] += v0; part[1][1] += v1; }
        else    { part[0][0] += v0; part[0][1] += v1; }
    }

    // red[side][col][rg]
    #pragma unroll
    for (int sdd = 0; sdd < 2; sdd++) {
        red[(sdd*64 + tx)*16 + rg]      = part[sdd][0];
        red[(sdd*64 + tx + 32)*16 + rg] = part[sdd][1];
    }
    __syncthreads();
    if (t < 128) {
        const float* rp = red + t*16;
        float s = 0.0f;
        #pragma unroll
        for (int i = 0; i < 16; i++) s += rp[i];
        g_part[blockIdx.x*128 + t] = s;
    }
}

// ---------------------------------------------------------------------------
// Kernel glob: combine per-block partials -> mean -> glob @ w2[64:,:].
// ---------------------------------------------------------------------------
__global__ void __launch_bounds__(64) k_glob(const float* __restrict__ w2)
{
    __shared__ float gl[64];
    const int g = blockIdx.x, c = threadIdx.x;
    const int b_start = (g * RR) >> 7;
    const int b_end   = (g * RR + RR - 1) >> 7;
    float s = 0.0f;
    for (int b = b_start; b <= b_end; b++) {
        int side = g - (b * 128) / RR;    // 0 or 1 by construction
        s += g_part[b*128 + side*64 + c];
    }
    gl[c] = s * (1.0f/374.0f);
    __syncthreads();
    if (c < 32) {
        float a = 0.0f;
        #pragma unroll
        for (int k = 0; k < 64; k++) a += gl[k] * w2[(64 + k)*32 + c];
        g_gcon[g*32 + c] = a;
    }
}

// ---------------------------------------------------------------------------
// Kernel 2: tiled GEMM (128 elements x 32 cols, K=64) + GELU + w3 head +
// softmax + Gumbel -> g_scores.
// ---------------------------------------------------------------------------
__global__ void __launch_bounds__(256) k2_scores(
    const float* __restrict__ w2, const float* __restrict__ b2,
    const float* __restrict__ w3, const float* __restrict__ b3,
    const float* __restrict__ u)
{
    __shared__ float ins[128*68];
    __shared__ float w2t[32*66];
    __shared__ float hbuf[128*34];
    __shared__ float w3s[64];
    __shared__ float b2s[32];
    __shared__ float b3s[2];

    const int t  = threadIdx.x;
    const int E0 = blockIdx.x * 128;

    #pragma unroll
    for (int i = 0; i < 8; i++) {
        int id = i*256 + t;
        int el = id >> 4, q = id & 15;
        float4 v = ((const float4*)g_local)[(size_t)(E0 + el)*16 + q];
        *(float4*)(ins + el*68 + q*4) = v;
    }
    #pragma unroll
    for (int i = 0; i < 8; i++) {
        int id = i*256 + t;
        int k = id >> 5, c = id & 31;
        w2t[c*66 + k] = w2[id];
    }
    if (t < 64) w3s[t] = w3[t];
    if (t < 32) b2s[t] = b2[t];
    if (t < 2)  b3s[t] = b3[t];
    __syncthreads();

    const int ty = t >> 4, tx = t & 15;
    u64 acc[8][2];
    #pragma unroll
    for (int i = 0; i < 8; i++) { acc[i][0] = 0ULL; acc[i][1] = 0ULL; }

    const u64* insu = (const u64*)ins;    // el stride 34
    const u64* w2u0 = (const u64*)(w2t + tx*66);
    const u64* w2u1 = (const u64*)(w2t + (tx+16)*66);
    #pragma unroll 4
    for (int k2 = 0; k2 < 32; k2++) {
        u64 b0 = w2u0[k2], b1 = w2u1[k2];
        #pragma unroll
        for (int i = 0; i < 8; i++) {
            u64 a = insu[(ty*8 + i)*34 + k2];
            acc[i][0] = fma2(a, b0, acc[i][0]);
            acc[i][1] = fma2(a, b1, acc[i][1]);
        }
    }

    #pragma unroll
    for (int i = 0; i < 8; i++) {
        int el = ty*8 + i;
        int bt = (E0 + el) / RR;
        const float* gc = g_gcon + bt*32;
        float lo, hi;
        upk2(acc[i][0], lo, hi);
        hbuf[el*34 + tx]      = gelu_exact(lo + hi + b2s[tx]      + gc[tx]);
        upk2(acc[i][1], lo, hi);
        hbuf[el*34 + tx + 16] = gelu_exact(lo + hi + b2s[tx + 16] + gc[tx + 16]);
    }
    __syncthreads();

    if (t < 128) {
        const float* h = hbuf + t*34;
        float z0 = b3s[0], z1 = b3s[1];
        #pragma unroll
        for (int g = 0; g < 32; g++) {
            float hv = h[g];
            z0 += hv * w3s[2*g];
            z1 += hv * w3s[2*g + 1];
        }
        float m  = fmaxf(z0, z1);
        float e0 = expf(z0 - m), e1 = expf(z1 - m);
        float score = e1 / (e0 + e1);
        float uu  = u[E0 + t];
        float gum = -logf(-logf(uu));
        g_scores[E0 + t] = score + gum;
    }
}

// ---------------------------------------------------------------------------
// Kernel 3: 299-step subset-operator scan, one warp per (b,t).
// Slim loop: kh = fma(ex,rinv,kh); ex *= max(fma(-ex,rinv,1), eps).
// ---------------------------------------------------------------------------
__global__ void __launch_bounds__(32) k3_scan(float* __restrict__ out)
{
    const int bt = blockIdx.x, lane = threadIdx.x;

    float ex[12], kh[12];
    #pragma unroll
    for (int j = 0; j < 12; j++) {
        int idx = j*32 + lane;
        ex[j] = (idx < RR) ? expf(g_scores[(size_t)bt*RR + idx]) : 0.0f;
        kh[j] = 0.0f;
    }

    #pragma unroll 1
    for (int it = 0; it < KSEL - 1; it++) {
        float z = (((ex[0] + ex[1]) + (ex[2] + ex[3])) +
                   ((ex[4] + ex[5]) + (ex[6] + ex[7]))) +
                  ((ex[8] + ex[9]) + (ex[10] + ex[11]));
        #pragma unroll
        for (int o = 16; o; o >>= 1) z += __shfl_xor_sync(0xffffffffu, z, o);
        float rinv = frcp(z);
        #pragma unroll
        for (int j = 0; j < 12; j++) {
            kh[j] = fmaf(ex[j], rinv, kh[j]);
            float m = fmaxf(fmaf(-ex[j], rinv, 1.0f), EPS_TINY);
            ex[j] *= m;
        }
    }
    {   // final iteration: khot update only
        float z = (((ex[0] + ex[1]) + (ex[2] + ex[3])) +
                   ((ex[4] + ex[5]) + (ex[6] + ex[7]))) +
                  ((ex[8] + ex[9]) + (ex[10] + ex[11]));
        #pragma unroll
        for (int o = 16; o; o >>= 1) z += __shfl_xor_sync(0xffffffffu, z, o);
        float rinv = frcp(z);
        #pragma unroll
        for (int j = 0; j < 12; j++) kh[j] = fmaf(ex[j], rinv, kh[j]);
    }

    #pragma unroll
    for (int j = 0; j < 12; j++) {
        int idx = j*32 + lane;
        if (idx < RR) out[(size_t)bt*RR + idx] = kh[j];
    }
}

// ---------------------------------------------------------------------------
// Kernel 4: stable top-K rank (value desc, ties -> lower index).
// One block per (b,t), one thread per index.
// ---------------------------------------------------------------------------
__global__ void __launch_bounds__(384) k4_rank(float* __restrict__ out)
{
    __shared__ float ks[RR];
    const int bt = blockIdx.x, t = threadIdx.x;
    if (t < RR) ks[t] = out[(size_t)bt*RR + t];
    __syncthreads();
    if (t >= RR) return;
    const float mine = ks[t];
    int rank = 0;
    #pragma unroll 4
    for (int i = 0; i < RR; i++) {
        float kv = ks[i];
        rank += (kv > mine) || (kv == mine && i < t);
    }
    if (rank < KSEL)
        out[(size_t)NROWS + (size_t)bt*KSEL + rank] = (float)t;
}

// ---------------------------------------------------------------------------
extern "C" void kernel_launch(void* const* d_in, const int* in_sizes, int n_in,
                              void* d_out, int out_size)
{
    const float* x   = (const float*)d_in[0];
    const float* u   = (const float*)d_in[1];
    const float* lnw = (const float*)d_in[2];
    const float* lnb = (const float*)d_in[3];
    const float* w1  = (const float*)d_in[4];
    const float* b1  = (const float*)d_in[5];
    const float* w2  = (const float*)d_in[6];
    const float* b2  = (const float*)d_in[7];
    const float* w3  = (const float*)d_in[8];
    const float* b3  = (const float*)d_in[9];
    float* out = (float*)d_out;

    const size_t smem1 = (size_t)(2*128*132 + 2*64*16) * sizeof(float); // 143360 B
    cudaFuncSetAttribute(k1_ln_gemm1, cudaFuncAttributeMaxDynamicSharedMemorySize,
                         (int)smem1);

    k1_ln_gemm1<<<NBLK1, 512, smem1>>>(x, lnw, lnb, w1, b1);
    k_glob<<<BT, 64>>>(w2);
    k2_scores<<<NBLK1, 256>>>(w2, b2, w3, b3, u);
    k3_scan<<<BT, 32>>>(out);
    k4_rank<<<BT, 384>>>(out);
}

// round 5
// speedup vs baseline: 1.0847x; 1.0847x over previous
#include <cuda_runtime.h>
#include <math.h>

#define NROWS (64*9*374)      // 215424 rows of F=128
#define BT    (64*9)          // 576 (b,t) groups
#define RR    374
#define KSEL  299
#define NBLK1 (NROWS/128)     // 1683 k1 blocks (exact)
#define EPS_TINY 1.17549435082228750797e-38f

typedef unsigned long long u64;

// scratch (static device memory — no runtime allocation)
__device__ __align__(16) float g_acc32[(size_t)NROWS*32]; // local @ w2[:64]
__device__ float g_part[NBLK1*128];                       // per-block hi partials
__device__ float g_gcon[BT*32];                           // glob @ w2[64:,:]
__device__ float g_scores[NROWS];                         // score + gumbel

__device__ __forceinline__ u64 fma2(u64 a, u64 b, u64 c) {
    u64 d; asm("fma.rn.f32x2 %0,%1,%2,%3;" : "=l"(d) : "l"(a), "l"(b), "l"(c));
    return d;
}
__device__ __forceinline__ void upk2(u64 v, float& lo, float& hi) {
    asm("mov.b64 {%0,%1},%2;" : "=f"(lo), "=f"(hi) : "l"(v));
}
__device__ __forceinline__ float frcp(float x) {
    float r; asm("rcp.approx.ftz.f32 %0,%1;" : "=f"(r) : "f"(x));
    return r;
}
__device__ __forceinline__ float gelu_exact(float x) {
    return 0.5f * x * (1.0f + erff(x * 0.70710678118654752440f));
}

// ---------------------------------------------------------------------------
// Kernel 1: LayerNorm + GEMM1 (128x128) + GELU + fused stage-2 GEMM
// (gelu_local[128x64] @ w2[:64,:32]) + glob partials.
// 256 threads, 128-row tile, 8x8 microtile (R3 config), f32x2 over K.
// ---------------------------------------------------------------------------
__global__ void __launch_bounds__(256) k1_ln_gemm1(
    const float* __restrict__ x, const float* __restrict__ ln_w,
    const float* __restrict__ ln_b, const float* __restrict__ w1,
    const float* __restrict__ b1, const float* __restrict__ w2)
{
    extern __shared__ float sm[];
    float* w1t = sm;                      // [128 cols][130]; later hlocal+w2t
    float* xs  = sm + 128*130;            // [128 rows][132]
    float* red = sm + 128*130 + 128*132;  // [2][64][16]
    float* hlocal = sm;                   // [128 rows][66] (reuses w1t)
    float* w2t    = sm + 128*66;          // [32 cols][66]

    const int t  = threadIdx.x;
    const int R0 = blockIdx.x * 128;

    // stage w1 transposed
    #pragma unroll
    for (int i = 0; i < 16; i++) {
        int id = i*256 + t;              // k = id/32, c4 = (id%32)*4
        int k  = id >> 5, c4 = (id & 31) << 2;
        float4 v = ((const float4*)w1)[id];
        w1t[(c4+0)*130 + k] = v.x;
        w1t[(c4+1)*130 + k] = v.y;
        w1t[(c4+2)*130 + k] = v.z;
        w1t[(c4+3)*130 + k] = v.w;
    }

    // layernorm: 8 warps x 16 rows
    {
        const int lane = t & 31, w = t >> 5;
        float4 lw = ((const float4*)ln_w)[lane];
        float4 lb = ((const float4*)ln_b)[lane];
        #pragma unroll
        for (int rr = 0; rr < 16; rr++) {
            int r = w*16 + rr;
            float4 xv = ((const float4*)x)[(size_t)(R0 + r)*32 + lane];
            float s = xv.x + xv.y + xv.z + xv.w;
            #pragma unroll
            for (int o = 16; o; o >>= 1) s += __shfl_xor_sync(0xffffffffu, s, o);
            float m = s * (1.0f/128.0f);
            float dx = xv.x - m, dy = xv.y - m, dz = xv.z - m, dw = xv.w - m;
            float q = dx*dx + dy*dy + dz*dz + dw*dw;
            #pragma unroll
            for (int o = 16; o; o >>= 1) q += __shfl_xor_sync(0xffffffffu, q, o);
            float rs = rsqrtf(q * (1.0f/128.0f) + 1e-5f);
            float4 y;
            y.x = dx*rs*lw.x + lb.x;
            y.y = dy*rs*lw.y + lb.y;
            y.z = dz*rs*lw.z + lb.z;
            y.w = dw*rs*lw.w + lb.w;
            *(float4*)(xs + r*132 + lane*4) = y;
        }
    }
    __syncthreads();

    const int ty = t >> 4, tx = t & 15;   // rows ty*8+i, cols tx + j*16
    {
        u64 acc[8][8];
        #pragma unroll
        for (int i = 0; i < 8; i++)
            #pragma unroll
            for (int j = 0; j < 8; j++) acc[i][j] = 0ULL;

        const u64* xsu = (const u64*)xs;  // row stride 66 u64
        #pragma unroll 4
        for (int k2 = 0; k2 < 64; k2++) {
            u64 a[8];
            #pragma unroll
            for (int i = 0; i < 8; i++) a[i] = xsu[(ty*8 + i)*66 + k2];
            #pragma unroll
            for (int jh = 0; jh < 2; jh++) {
                u64 b[4];
                #pragma unroll
                for (int j = 0; j < 4; j++)
                    b[j] = ((const u64*)(w1t + (tx + (jh*4 + j)*16)*130))[k2];
                #pragma unroll
                for (int i = 0; i < 8; i++)
                    #pragma unroll
                    for (int j = 0; j < 4; j++)
                        acc[i][jh*4 + j] = fma2(a[i], b[j], acc[i][jh*4 + j]);
            }
        }
        __syncthreads();   // done reading w1t/xs; safe to overwrite w1t region

        float bv[8];
        #pragma unroll
        for (int j = 0; j < 8; j++) bv[j] = b1[tx + j*16];

        const int g0 = R0 / RR;
        const int boundary = (g0 + 1) * RR;
        float part[2][4];
        #pragma unroll
        for (int sdd = 0; sdd < 2; sdd++)
            #pragma unroll
            for (int j = 0; j < 4; j++) part[sdd][j] = 0.0f;

        #pragma unroll
        for (int i = 0; i < 8; i++) {
            int rg = R0 + ty*8 + i;
            int rl = ty*8 + i;
            // local half -> hlocal smem
            #pragma unroll
            for (int j = 0; j < 4; j++) {
                float lo, hi; upk2(acc[i][j], lo, hi);
                hlocal[rl*66 + tx + j*16] = gelu_exact(lo + hi + bv[j]);
            }
            // hi half -> glob partials
            int sd = (rg >= boundary) ? 1 : 0;
            #pragma unroll
            for (int j = 4; j < 8; j++) {
                float lo, hi; upk2(acc[i][j], lo, hi);
                float v = gelu_exact(lo + hi + bv[j]);
                if (sd) part[1][j-4] += v; else part[0][j-4] += v;
            }
        }

        // red[side][col][ty]
        #pragma unroll
        for (int sdd = 0; sdd < 2; sdd++)
            #pragma unroll
            for (int j = 0; j < 4; j++)
                red[((sdd*64) + (tx + j*16))*16 + ty] = part[sdd][j];
    }

    // stage transposed w2[:64,:32]
    #pragma unroll
    for (int i = 0; i < 8; i++) {
        int id = i*256 + t;              // k = id/32, c = id%32
        int k = id >> 5, c = id & 31;
        w2t[c*66 + k] = w2[id];
    }
    __syncthreads();

    // glob partial reduce -> g_part
    if (t < 128) {
        const float* rp = red + t*16;
        float s = 0.0f;
        #pragma unroll
        for (int i = 0; i < 16; i++) s += rp[i];
        g_part[blockIdx.x*128 + t] = s;
    }

    // stage-2 GEMM: hlocal[128x64] @ w2t -> g_acc32 (cols tx, tx+16)
    {
        u64 acc2[8][2];
        #pragma unroll
        for (int i = 0; i < 8; i++) { acc2[i][0] = 0ULL; acc2[i][1] = 0ULL; }

        const u64* hu   = (const u64*)hlocal;           // row stride 33
        const u64* w2u0 = (const u64*)(w2t + tx*66);
        const u64* w2u1 = (const u64*)(w2t + (tx+16)*66);
        #pragma unroll 4
        for (int k2 = 0; k2 < 32; k2++) {
            u64 b0 = w2u0[k2], b1 = w2u1[k2];
            #pragma unroll
            for (int i = 0; i < 8; i++) {
                u64 a = hu[(ty*8 + i)*33 + k2];
                acc2[i][0] = fma2(a, b0, acc2[i][0]);
                acc2[i][1] = fma2(a, b1, acc2[i][1]);
            }
        }
        #pragma unroll
        for (int i = 0; i < 8; i++) {
            size_t rg = (size_t)(R0 + ty*8 + i);
            float lo, hi;
            upk2(acc2[i][0], lo, hi);
            g_acc32[rg*32 + tx]      = lo + hi;
            upk2(acc2[i][1], lo, hi);
            g_acc32[rg*32 + tx + 16] = lo + hi;
        }
    }
}

// ---------------------------------------------------------------------------
// Kernel glob: combine per-block partials -> mean -> glob @ w2[64:,:].
// ---------------------------------------------------------------------------
__global__ void __launch_bounds__(64) k_glob(const float* __restrict__ w2)
{
    __shared__ float gl[64];
    const int g = blockIdx.x, c = threadIdx.x;
    const int b_start = (g * RR) >> 7;
    const int b_end   = (g * RR + RR - 1) >> 7;
    float s = 0.0f;
    for (int b = b_start; b <= b_end; b++) {
        int side = g - (b * 128) / RR;    // 0 or 1 by construction
        s += g_part[b*128 + side*64 + c];
    }
    gl[c] = s * (1.0f/374.0f);
    __syncthreads();
    if (c < 32) {
        float a = 0.0f;
        #pragma unroll
        for (int k = 0; k < 64; k++) a += gl[k] * w2[(64 + k)*32 + c];
        g_gcon[g*32 + c] = a;
    }
}

// ---------------------------------------------------------------------------
// Kernel 2 (elementwise): gelu(acc32 + gcon + b2) -> w3 head -> softmax ->
// score + Gumbel -> g_scores.  One thread per element.
// ---------------------------------------------------------------------------
__global__ void __launch_bounds__(256) k2_scores(
    const float* __restrict__ b2, const float* __restrict__ w3,
    const float* __restrict__ b3, const float* __restrict__ u)
{
    __shared__ float b2s[32];
    __shared__ float w3s[64];
    __shared__ float b3s[2];
    const int t = threadIdx.x;
    if (t < 32) b2s[t] = b2[t];
    if (t < 64) w3s[t] = w3[t];
    if (t < 2)  b3s[t] = b3[t];
    __syncthreads();

    const int e = blockIdx.x*256 + t;
    if (e >= NROWS) return;
    const int bt = e / RR;
    const float* gc = g_gcon + bt*32;

    float z0 = b3s[0], z1 = b3s[1];
    const float4* ap = (const float4*)(g_acc32 + (size_t)e*32);
    #pragma unroll
    for (int q = 0; q < 8; q++) {
        float4 a = ap[q];
        int c = q*4;
        float h0 = gelu_exact(a.x + b2s[c]   + gc[c]);
        float h1 = gelu_exact(a.y + b2s[c+1] + gc[c+1]);
        float h2 = gelu_exact(a.z + b2s[c+2] + gc[c+2]);
        float h3 = gelu_exact(a.w + b2s[c+3] + gc[c+3]);
        z0 += h0*w3s[2*c]   + h1*w3s[2*c+2] + h2*w3s[2*c+4] + h3*w3s[2*c+6];
        z1 += h0*w3s[2*c+1] + h1*w3s[2*c+3] + h2*w3s[2*c+5] + h3*w3s[2*c+7];
    }
    float m  = fmaxf(z0, z1);
    float e0 = expf(z0 - m), e1 = expf(z1 - m);
    float score = e1 / (e0 + e1);
    float uu  = u[e];
    float gum = -logf(-logf(uu));
    g_scores[e] = score + gum;
}

// ---------------------------------------------------------------------------
// Kernel 3: 299-step subset-operator scan, one warp per (b,t).
// ---------------------------------------------------------------------------
__global__ void __launch_bounds__(32) k3_scan(float* __restrict__ out)
{
    const int bt = blockIdx.x, lane = threadIdx.x;

    float ex[12], kh[12];
    #pragma unroll
    for (int j = 0; j < 12; j++) {
        int idx = j*32 + lane;
        ex[j] = (idx < RR) ? expf(g_scores[(size_t)bt*RR + idx]) : 0.0f;
        kh[j] = 0.0f;
    }

    #pragma unroll 1
    for (int it = 0; it < KSEL - 1; it++) {
        float z = (((ex[0] + ex[1]) + (ex[2] + ex[3])) +
                   ((ex[4] + ex[5]) + (ex[6] + ex[7]))) +
                  ((ex[8] + ex[9]) + (ex[10] + ex[11]));
        #pragma unroll
        for (int o = 16; o; o >>= 1) z += __shfl_xor_sync(0xffffffffu, z, o);
        float rinv = frcp(z);
        #pragma unroll
        for (int j = 0; j < 12; j++) {
            kh[j] = fmaf(ex[j], rinv, kh[j]);
            float m = fmaxf(fmaf(-ex[j], rinv, 1.0f), EPS_TINY);
            ex[j] *= m;
        }
    }
    {
        float z = (((ex[0] + ex[1]) + (ex[2] + ex[3])) +
                   ((ex[4] + ex[5]) + (ex[6] + ex[7]))) +
                  ((ex[8] + ex[9]) + (ex[10] + ex[11]));
        #pragma unroll
        for (int o = 16; o; o >>= 1) z += __shfl_xor_sync(0xffffffffu, z, o);
        float rinv = frcp(z);
        #pragma unroll
        for (int j = 0; j < 12; j++) kh[j] = fmaf(ex[j], rinv, kh[j]);
    }

    #pragma unroll
    for (int j = 0; j < 12; j++) {
        int idx = j*32 + lane;
        if (idx < RR) out[(size_t)bt*RR + idx] = kh[j];
    }
}

// ---------------------------------------------------------------------------
// Kernel 4: stable top-K rank (value desc, ties -> lower index).
// ---------------------------------------------------------------------------
__global__ void __launch_bounds__(384) k4_rank(float* __restrict__ out)
{
    __shared__ float ks[RR];
    const int bt = blockIdx.x, t = threadIdx.x;
    if (t < RR) ks[t] = out[(size_t)bt*RR + t];
    __syncthreads();
    if (t >= RR) return;
    const float mine = ks[t];
    int rank = 0;
    #pragma unroll 4
    for (int i = 0; i < RR; i++) {
        float kv = ks[i];
        rank += (kv > mine) || (kv == mine && i < t);
    }
    if (rank < KSEL)
        out[(size_t)NROWS + (size_t)bt*KSEL + rank] = (float)t;
}

// ---------------------------------------------------------------------------
extern "C" void kernel_launch(void* const* d_in, const int* in_sizes, int n_in,
                              void* d_out, int out_size)
{
    const float* x   = (const float*)d_in[0];
    const float* u   = (const float*)d_in[1];
    const float* lnw = (const float*)d_in[2];
    const float* lnb = (const float*)d_in[3];
    const float* w1  = (const float*)d_in[4];
    const float* b1  = (const float*)d_in[5];
    const float* w2  = (const float*)d_in[6];
    const float* b2  = (const float*)d_in[7];
    const float* w3  = (const float*)d_in[8];
    const float* b3  = (const float*)d_in[9];
    float* out = (float*)d_out;

    const size_t smem1 = (size_t)(128*130 + 128*132 + 2*64*16) * sizeof(float); // 142336 B
    cudaFuncSetAttribute(k1_ln_gemm1, cudaFuncAttributeMaxDynamicSharedMemorySize,
                         (int)smem1);

    k1_ln_gemm1<<<NBLK1, 256, smem1>>>(x, lnw, lnb, w1, b1, w2);
    k_glob<<<BT, 64>>>(w2);
    k2_scores<<<(NROWS + 255)/256, 256>>>(b2, w3, b3, u);
    k3_scan<<<BT, 32>>>(out);
    k4_rank<<<BT, 384>>>(out);
}

// round 7
// speedup vs baseline: 1.2569x; 1.1587x over previous
#include <cuda_runtime.h>
#include <math.h>

#define NROWS (64*9*374)      // 215424 rows of F=128
#define BT    (64*9)          // 576 (b,t) groups
#define RR    374
#define KSEL  299
#define NBLK1 (NROWS/64)      // 3366 k1 blocks (64 rows each, exact)
#define EPS_TINY 1.17549435082228750797e-38f

typedef unsigned long long u64;

// scratch (static device memory — no runtime allocation)
__device__ __align__(16) float g_acc32[(size_t)NROWS*32]; // local @ w2[:64]
__device__ float g_part[NBLK1*128];                       // per-block hi partials
__device__ float g_gcon[BT*32];                           // glob @ w2[64:,:]
__device__ float g_scores[NROWS];                         // score + gumbel

__device__ __forceinline__ u64 fma2(u64 a, u64 b, u64 c) {
    u64 d; asm("fma.rn.f32x2 %0,%1,%2,%3;" : "=l"(d) : "l"(a), "l"(b), "l"(c));
    return d;
}
__device__ __forceinline__ u64 pk2(float lo, float hi) {
    u64 r; asm("mov.b64 %0,{%1,%2};" : "=l"(r) : "f"(lo), "f"(hi));
    return r;
}
__device__ __forceinline__ void upk2(u64 v, float& lo, float& hi) {
    asm("mov.b64 {%0,%1},%2;" : "=f"(lo), "=f"(hi) : "l"(v));
}
__device__ __forceinline__ float frcp(float x) {
    float r; asm("rcp.approx.ftz.f32 %0,%1;" : "=f"(r) : "f"(x));
    return r;
}
__device__ __forceinline__ float gelu_exact(float x) {
    return 0.5f * x * (1.0f + erff(x * 0.70710678118654752440f));
}

// ---------------------------------------------------------------------------
// Kernel 1: LayerNorm + GEMM1 (64x128 tile, K=128) + GELU + fused stage-2
// GEMM (gelu_local[64x64] @ w2[:64,:32]) + glob partials.
// 256 threads, 2 blocks/SM (110KB smem). f32x2 paired over COLUMNS:
// w1 stays k-major (no transpose), b = LDS.128 conflict-free,
// a = broadcast LDS.64 of (x_k, x_{k+1}) repacked as {x_k,x_k}.
// Thread tile: 4 rows x 8 cols (cols 4tx..4tx+3 local, 4tx+64..+67 hi).
// hlocal row stride 68 floats (272B = 16B multiple) for aligned STS.128.
// ---------------------------------------------------------------------------
__global__ void __launch_bounds__(256, 2) k1_ln_gemm1(
    const float* __restrict__ x, const float* __restrict__ ln_w,
    const float* __restrict__ ln_b, const float* __restrict__ w1,
    const float* __restrict__ b1, const float* __restrict__ w2)
{
    extern __shared__ float sm[];
    float* w1s = sm;                      // [128 k][132]  (k-major)
    float* xs  = sm + 128*132;            // [64 rows][132]
    float* red = sm + 128*132 + 64*132;   // [2][64][17]
    float* hlocal = sm;                   // [64 rows][68]   (reuses w1s)
    float* w2t    = sm + 64*68;           // [32 cols][66]   (reuses w1s)

    const int t  = threadIdx.x;
    const int R0 = blockIdx.x * 64;

    // stage w1 k-major (no transpose; coalesced float4 both sides)
    #pragma unroll
    for (int i = 0; i < 16; i++) {
        int id = i*256 + t;              // k = id/32, c4 = (id%32)*4
        int k  = id >> 5, c4 = (id & 31) << 2;
        float4 v = ((const float4*)w1)[id];
        *(float4*)(w1s + k*132 + c4) = v;
    }

    // layernorm: 8 warps x 8 rows
    {
        const int lane = t & 31, w = t >> 5;
        float4 lw = ((const float4*)ln_w)[lane];
        float4 lb = ((const float4*)ln_b)[lane];
        #pragma unroll
        for (int rr = 0; rr < 8; rr++) {
            int r = w*8 + rr;
            float4 xv = ((const float4*)x)[(size_t)(R0 + r)*32 + lane];
            float s = xv.x + xv.y + xv.z + xv.w;
            #pragma unroll
            for (int o = 16; o; o >>= 1) s += __shfl_xor_sync(0xffffffffu, s, o);
            float m = s * (1.0f/128.0f);
            float dx = xv.x - m, dy = xv.y - m, dz = xv.z - m, dw = xv.w - m;
            float q = dx*dx + dy*dy + dz*dz + dw*dw;
            #pragma unroll
            for (int o = 16; o; o >>= 1) q += __shfl_xor_sync(0xffffffffu, q, o);
            float rs = rsqrtf(q * (1.0f/128.0f) + 1e-5f);
            float4 y;
            y.x = dx*rs*lw.x + lb.x;
            y.y = dy*rs*lw.y + lb.y;
            y.z = dz*rs*lw.z + lb.z;
            y.w = dw*rs*lw.w + lb.w;
            *(float4*)(xs + r*132 + lane*4) = y;
        }
    }
    __syncthreads();

    const int ty = t >> 4, tx = t & 15;   // rows 4ty..4ty+3, cols 4tx+{0..3,64..67}
    float part[2][4];
    {
        u64 acc[4][4];                    // [row][colpair]: cp 0,1 local; 2,3 hi
        #pragma unroll
        for (int i = 0; i < 4; i++)
            #pragma unroll
            for (int j = 0; j < 4; j++) acc[i][j] = 0ULL;

        #pragma unroll 4
        for (int k2 = 0; k2 < 64; k2++) { // two k per iteration
            int k = k2*2;
            // a: (x_k, x_{k+1}) broadcast, repack
            u64 a0[4], a1[4];
            #pragma unroll
            for (int i = 0; i < 4; i++) {
                float2 av = *(const float2*)(xs + (ty*4 + i)*132 + k);
                a0[i] = pk2(av.x, av.x);
                a1[i] = pk2(av.y, av.y);
            }
            // b: LDS.128 x2 per k (local quad + hi quad)
            float4 bl0 = *(const float4*)(w1s + k*132 + tx*4);
            float4 bh0 = *(const float4*)(w1s + k*132 + tx*4 + 64);
            float4 bl1 = *(const float4*)(w1s + (k+1)*132 + tx*4);
            float4 bh1 = *(const float4*)(w1s + (k+1)*132 + tx*4 + 64);
            const u64* l0 = (const u64*)&bl0;
            const u64* h0 = (const u64*)&bh0;
            const u64* l1 = (const u64*)&bl1;
            const u64* h1 = (const u64*)&bh1;
            #pragma unroll
            for (int i = 0; i < 4; i++) {
                acc[i][0] = fma2(a0[i], l0[0], acc[i][0]);
                acc[i][1] = fma2(a0[i], l0[1], acc[i][1]);
                acc[i][2] = fma2(a0[i], h0[0], acc[i][2]);
                acc[i][3] = fma2(a0[i], h0[1], acc[i][3]);
                acc[i][0] = fma2(a1[i], l1[0], acc[i][0]);
                acc[i][1] = fma2(a1[i], l1[1], acc[i][1]);
                acc[i][2] = fma2(a1[i], h1[0], acc[i][2]);
                acc[i][3] = fma2(a1[i], h1[1], acc[i][3]);
            }
        }
        __syncthreads();   // done reading w1s/xs; w1s region reusable

        float4 bl = *(const float4*)(b1 + tx*4);
        float4 bh = *(const float4*)(b1 + tx*4 + 64);

        const int g0 = R0 / RR;
        const int boundary = (g0 + 1) * RR;
        #pragma unroll
        for (int sdd = 0; sdd < 2; sdd++)
            #pragma unroll
            for (int j = 0; j < 4; j++) part[sdd][j] = 0.0f;

        #pragma unroll
        for (int i = 0; i < 4; i++) {
            int rg = R0 + ty*4 + i;
            int rl = ty*4 + i;
            // local half -> hlocal smem (float4, 16B-aligned: stride 68)
            float4 hv;
            float lo, hi;
            upk2(acc[i][0], lo, hi); hv.x = gelu_exact(lo + bl.x); hv.y = gelu_exact(hi + bl.y);
            upk2(acc[i][1], lo, hi); hv.z = gelu_exact(lo + bl.z); hv.w = gelu_exact(hi + bl.w);
            *(float4*)(hlocal + rl*68 + tx*4) = hv;
            // hi half -> glob partials
            int sd = (rg >= boundary) ? 1 : 0;
            float v0, v1, v2, v3;
            upk2(acc[i][2], lo, hi); v0 = gelu_exact(lo + bh.x); v1 = gelu_exact(hi + bh.y);
            upk2(acc[i][3], lo, hi); v2 = gelu_exact(lo + bh.z); v3 = gelu_exact(hi + bh.w);
            if (sd) { part[1][0]+=v0; part[1][1]+=v1; part[1][2]+=v2; part[1][3]+=v3; }
            else    { part[0][0]+=v0; part[0][1]+=v1; part[0][2]+=v2; part[0][3]+=v3; }
        }
    }

    // red[side][col][ty], stride 17
    #pragma unroll
    for (int sdd = 0; sdd < 2; sdd++)
        #pragma unroll
        for (int j = 0; j < 4; j++)
            red[(sdd*64 + tx*4 + j)*17 + ty] = part[sdd][j];

    // stage transposed w2[:64,:32] into w2t (after w1s freed)
    #pragma unroll
    for (int i = 0; i < 8; i++) {
        int id = i*256 + t;              // k = id/32, c = id%32
        int k = id >> 5, c = id & 31;
        w2t[c*66 + k] = w2[id];
    }
    __syncthreads();

    // glob partial reduce -> g_part
    if (t < 128) {
        const float* rp = red + t*17;
        float s = 0.0f;
        #pragma unroll
        for (int i = 0; i < 16; i++) s += rp[i];
        g_part[blockIdx.x*128 + t] = s;
    }

    // stage-2 GEMM: hlocal[64x64] @ w2t -> g_acc32 (cols tx, tx+16), K paired
    {
        u64 acc2[4][2];
        #pragma unroll
        for (int i = 0; i < 4; i++) { acc2[i][0] = 0ULL; acc2[i][1] = 0ULL; }

        const u64* hu   = (const u64*)hlocal;           // row stride 34 u64
        const u64* w2u0 = (const u64*)(w2t + tx*66);
        const u64* w2u1 = (const u64*)(w2t + (tx+16)*66);
        #pragma unroll 8
        for (int k2 = 0; k2 < 32; k2++) {
            u64 b0 = w2u0[k2], b1v = w2u1[k2];
            #pragma unroll
            for (int i = 0; i < 4; i++) {
                u64 a = hu[(ty*4 + i)*34 + k2];
                acc2[i][0] = fma2(a, b0,  acc2[i][0]);
                acc2[i][1] = fma2(a, b1v, acc2[i][1]);
            }
        }
        #pragma unroll
        for (int i = 0; i < 4; i++) {
            size_t rg = (size_t)(R0 + ty*4 + i);
            float lo, hi;
            upk2(acc2[i][0], lo, hi);
            g_acc32[rg*32 + tx]      = lo + hi;
            upk2(acc2[i][1], lo, hi);
            g_acc32[rg*32 + tx + 16] = lo + hi;
        }
    }
}

// ---------------------------------------------------------------------------
// Kernel glob: combine per-block partials -> mean -> glob @ w2[64:,:].
// ---------------------------------------------------------------------------
__global__ void __launch_bounds__(64) k_glob(const float* __restrict__ w2)
{
    __shared__ float gl[64];
    const int g = blockIdx.x, c = threadIdx.x;
    const int b_start = (g * RR) >> 6;
    const int b_end   = (g * RR + RR - 1) >> 6;
    float s = 0.0f;
    for (int b = b_start; b <= b_end; b++) {
        int side = g - (b * 64) / RR;     // 0 or 1 by construction
        s += g_part[b*128 + side*64 + c];
    }
    gl[c] = s * (1.0f/374.0f);
    __syncthreads();
    if (c < 32) {
        float a = 0.0f;
        #pragma unroll
        for (int k = 0; k < 64; k++) a += gl[k] * w2[(64 + k)*32 + c];
        g_gcon[g*32 + c] = a;
    }
}

// ---------------------------------------------------------------------------
// Kernel 2 (elementwise): gelu(acc32 + gcon + b2) -> w3 head -> softmax ->
// score + Gumbel -> g_scores.
// ---------------------------------------------------------------------------
__global__ void __launch_bounds__(256) k2_scores(
    const float* __restrict__ b2, const float* __restrict__ w3,
    const float* __restrict__ b3, const float* __restrict__ u)
{
    __shared__ float b2s[32];
    __shared__ float w3s[64];
    __shared__ float b3s[2];
    const int t = threadIdx.x;
    if (t < 32) b2s[t] = b2[t];
    if (t < 64) w3s[t] = w3[t];
    if (t < 2)  b3s[t] = b3[t];
    __syncthreads();

    const int e = blockIdx.x*256 + t;
    if (e >= NROWS) return;
    const int bt = e / RR;
    const float* gc = g_gcon + bt*32;

    float z0 = b3s[0], z1 = b3s[1];
    const float4* ap = (const float4*)(g_acc32 + (size_t)e*32);
    #pragma unroll
    for (int q = 0; q < 8; q++) {
        float4 a = ap[q];
        int c = q*4;
        float h0 = gelu_exact(a.x + b2s[c]   + gc[c]);
        float h1 = gelu_exact(a.y + b2s[c+1] + gc[c+1]);
        float h2 = gelu_exact(a.z + b2s[c+2] + gc[c+2]);
        float h3 = gelu_exact(a.w + b2s[c+3] + gc[c+3]);
        z0 += h0*w3s[2*c]   + h1*w3s[2*c+2] + h2*w3s[2*c+4] + h3*w3s[2*c+6];
        z1 += h0*w3s[2*c+1] + h1*w3s[2*c+3] + h2*w3s[2*c+5] + h3*w3s[2*c+7];
    }
    float m  = fmaxf(z0, z1);
    float e0 = expf(z0 - m), e1 = expf(z1 - m);
    float score = e1 / (e0 + e1);
    float uu  = u[e];
    float gum = -logf(-logf(uu));
    g_scores[e] = score + gum;
}

// ---------------------------------------------------------------------------
// Kernel 3: 299-step subset-operator scan, one warp per (b,t).
// ---------------------------------------------------------------------------
__global__ void __launch_bounds__(32) k3_scan(float* __restrict__ out)
{
    const int bt = blockIdx.x, lane = threadIdx.x;

    float ex[12], kh[12];
    #pragma unroll
    for (int j = 0; j < 12; j++) {
        int idx = j*32 + lane;
        ex[j] = (idx < RR) ? expf(g_scores[(size_t)bt*RR + idx]) : 0.0f;
        kh[j] = 0.0f;
    }

    #pragma unroll 1
    for (int it = 0; it < KSEL - 1; it++) {
        float z = (((ex[0] + ex[1]) + (ex[2] + ex[3])) +
                   ((ex[4] + ex[5]) + (ex[6] + ex[7]))) +
                  ((ex[8] + ex[9]) + (ex[10] + ex[11]));
        #pragma unroll
        for (int o = 16; o; o >>= 1) z += __shfl_xor_sync(0xffffffffu, z, o);
        float rinv = frcp(z);
        #pragma unroll
        for (int j = 0; j < 12; j++) {
            kh[j] = fmaf(ex[j], rinv, kh[j]);
            float m = fmaxf(fmaf(-ex[j], rinv, 1.0f), EPS_TINY);
            ex[j] *= m;
        }
    }
    {
        float z = (((ex[0] + ex[1]) + (ex[2] + ex[3])) +
                   ((ex[4] + ex[5]) + (ex[6] + ex[7]))) +
                  ((ex[8] + ex[9]) + (ex[10] + ex[11]));
        #pragma unroll
        for (int o = 16; o; o >>= 1) z += __shfl_xor_sync(0xffffffffu, z, o);
        float rinv = frcp(z);
        #pragma unroll
        for (int j = 0; j < 12; j++) kh[j] = fmaf(ex[j], rinv, kh[j]);
    }

    #pragma unroll
    for (int j = 0; j < 12; j++) {
        int idx = j*32 + lane;
        if (idx < RR) out[(size_t)bt*RR + idx] = kh[j];
    }
}

// ---------------------------------------------------------------------------
// Kernel 4: stable top-K rank (value desc, ties -> lower index).
// ---------------------------------------------------------------------------
__global__ void __launch_bounds__(384) k4_rank(float* __restrict__ out)
{
    __shared__ float ks[RR];
    const int bt = blockIdx.x, t = threadIdx.x;
    if (t < RR) ks[t] = out[(size_t)bt*RR + t];
    __syncthreads();
    if (t >= RR) return;
    const float mine = ks[t];
    int rank = 0;
    #pragma unroll 4
    for (int i = 0; i < RR; i++) {
        float kv = ks[i];
        rank += (kv > mine) || (kv == mine && i < t);
    }
    if (rank < KSEL)
        out[(size_t)NROWS + (size_t)bt*KSEL + rank] = (float)t;
}

// ---------------------------------------------------------------------------
extern "C" void kernel_launch(void* const* d_in, const int* in_sizes, int n_in,
                              void* d_out, int out_size)
{
    const float* x   = (const float*)d_in[0];
    const float* u   = (const float*)d_in[1];
    const float* lnw = (const float*)d_in[2];
    const float* lnb = (const float*)d_in[3];
    const float* w1  = (const float*)d_in[4];
    const float* b1  = (const float*)d_in[5];
    const float* w2  = (const float*)d_in[6];
    const float* b2  = (const float*)d_in[7];
    const float* w3  = (const float*)d_in[8];
    const float* b3  = (const float*)d_in[9];
    float* out = (float*)d_out;

    // w1s 128*132 + xs 64*132 + red 2*64*17 = 27520 floats = 110080 B
    const size_t smem1 = (size_t)(128*132 + 64*132 + 2*64*17) * sizeof(float);
    cudaFuncSetAttribute(k1_ln_gemm1, cudaFuncAttributeMaxDynamicSharedMemorySize,
                         (int)smem1);

    k1_ln_gemm1<<<NBLK1, 256, smem1>>>(x, lnw, lnb, w1, b1, w2);
    k_glob<<<BT, 64>>>(w2);
    k2_scores<<<(NROWS + 255)/256, 256>>>(b2, w3, b3, u);
    k3_scan<<<BT, 32>>>(out);
    k4_rank<<<BT, 384>>>(out);
}